// round 14
// baseline (speedup 1.0000x reference)
#include <cuda_runtime.h>

#define NB     4
#define NPTS   8192
#define TPB    128
#define QBLK   512            // queries per block (128 per warp)
#define TBLK   256            // targets per block (8 per lane, shared by all 4 warps)
#define ASZ    (NB*NPTS)      // 32768 points per array
#define NCTA   2048           // grid size
#define NSLICE 64             // reduction slices (done by last 64 CTAs)

// Scratch (static device globals, zero-initialized at module load; no allocations):
// g_enc[idx] = ~fenc(min_m) where m = d/2 (symmetric half-distance).
//   region 0: per-a1-point min (dist1) ; region 1 (+ASZ): per-a2-point min (dist2).
// 0 is the +inf identity for atomicMax; reduction resets entries to 0 every replay.
__device__ unsigned g_enc[2*ASZ];
__device__ float    g_part[NSLICE];
__device__ unsigned g_tk1, g_tk2;    // zero-init; self-resetting tickets

__device__ __forceinline__ unsigned long long pk2(float lo, float hi) {
    unsigned long long r;
    asm("mov.b64 %0, {%1,%2};" : "=l"(r) : "f"(lo), "f"(hi));
    return r;
}
// Order-preserving float->uint (handles negatives): increasing.
__device__ __forceinline__ unsigned fenc(float f) {
    unsigned b = __float_as_uint(f);
    return b ^ ((b & 0x80000000u) ? 0xFFFFFFFFu : 0x80000000u);
}
__device__ __forceinline__ float fdec(unsigned u) {   // inverse of fenc
    unsigned b = (u & 0x80000000u) ? (u ^ 0x80000000u) : ~u;
    return __uint_as_float(b);
}

// ONE kernel, symmetric: every (a1,a2) pair evaluated EXACTLY ONCE, feeding both
// the row (a1) and column (a2) mins. grid (16, 32, 4) = 2048 CTAs.
//   blockIdx.x: a1 query tile (512) ; blockIdx.y: a2 target tile (256) ; z: batch.
// Lane owns 8 targets in registers (4 packed pairs); queries stream from smem.
__global__ __launch_bounds__(TPB) void chamfer_kernel(const float* __restrict__ q1,
                                                      const float* __restrict__ q2,
                                                      float* __restrict__ out) {
    int b  = blockIdx.z;
    int t  = threadIdx.x;
    int ln = t & 31;

    // qsh[q*4 + {0,1,2,3}] = (x,x),(y,y),(z,z),(hq,hq) packed 64-bit. 16 KB.
    __shared__ unsigned long long qsh[QBLK * 4];
    __shared__ float              tsm[TBLK * 3];   // raw target staging, 3 KB
    __shared__ float              ws_dummy;        // (kept for layout clarity)
    __shared__ unsigned           s_tk;
    __shared__ float              wsum[4];

    // ---- Stage queries: 512 a1 points -> packed splats (4 queries per thread) ----
    {
        const float4* qsrc = (const float4*)(q1 + (size_t)(b * NPTS + blockIdx.x * QBLK) * 3);
        float4 A = qsrc[3*t], B = qsrc[3*t + 1], C = qsrc[3*t + 2];
        // queries 4t..4t+3: (A.x,A.y,A.z) (A.w,B.x,B.y) (B.z,B.w,C.x) (C.y,C.z,C.w)
        float h0 = 0.5f*(A.x*A.x + A.y*A.y + A.z*A.z);
        float h1 = 0.5f*(A.w*A.w + B.x*B.x + B.y*B.y);
        float h2 = 0.5f*(B.z*B.z + B.w*B.w + C.x*C.x);
        float h3 = 0.5f*(C.y*C.y + C.z*C.z + C.w*C.w);
        unsigned long long* d0 = &qsh[(4*t) * 4];
        d0[0]  = pk2(A.x, A.x); d0[1]  = pk2(A.y, A.y); d0[2]  = pk2(A.z, A.z); d0[3]  = pk2(h0, h0);
        d0[4]  = pk2(A.w, A.w); d0[5]  = pk2(B.x, B.x); d0[6]  = pk2(B.y, B.y); d0[7]  = pk2(h1, h1);
        d0[8]  = pk2(B.z, B.z); d0[9]  = pk2(B.w, B.w); d0[10] = pk2(C.x, C.x); d0[11] = pk2(h2, h2);
        d0[12] = pk2(C.y, C.y); d0[13] = pk2(C.z, C.z); d0[14] = pk2(C.w, C.w); d0[15] = pk2(h3, h3);
    }
    // ---- Stage targets raw: 256 a2 points = 192 float4 ----
    {
        const float4* tsrc = (const float4*)(q2 + (size_t)(b * NPTS + blockIdx.y * TBLK) * 3);
        float4* dst = (float4*)tsm;
        for (int i = t; i < (TBLK * 3) / 4; i += TPB) dst[i] = tsrc[i];
    }
    __syncthreads();

    // ---- Lane-private targets: 4 packed pairs {(-x0,-x1),(-y0,-y1),(-z0,-z1),(h0,h1)} ----
    unsigned long long NX[4], NY[4], NZ[4], HT[4];
    float cl[8];                                   // per-target column mins (m = d/2)
#pragma unroll
    for (int j = 0; j < 4; j++) {
        const float* p = &tsm[(ln * 8 + 2 * j) * 3];
        float x0 = p[0], y0 = p[1], z0 = p[2];
        float x1 = p[3], y1 = p[4], z1 = p[5];
        NX[j] = pk2(-x0, -x1);
        NY[j] = pk2(-y0, -y1);
        NZ[j] = pk2(-z0, -z1);
        HT[j] = pk2(0.5f*(x0*x0 + y0*y0 + z0*z0), 0.5f*(x1*x1 + y1*y1 + z1*z1));
        cl[2*j] = __int_as_float(0x7f800000);
        cl[2*j + 1] = __int_as_float(0x7f800000);
    }

    unsigned* enc1 = g_enc + b * NPTS + blockIdx.x * QBLK;          // a1 mins
    unsigned* enc2 = g_enc + ASZ + b * NPTS + blockIdx.y * TBLK;    // a2 mins
    int qoff = (t >> 5) * 128;                     // warp's query quarter

    // ---- Main loop: 128 queries per warp, 8 unique evals per lane per query ----
#pragma unroll 2
    for (int qi = 0; qi < 128; ++qi) {
        int q = qoff + qi;
        const ulonglong2* qp = (const ulonglong2*)&qsh[q * 4];      // broadcast LDS.128
        ulonglong2 qa = qp[0];                     // X2, Y2
        ulonglong2 qb = qp[1];                     // Z2, HQ2

        unsigned long long m[4];
        // m = hq + ht - (x*xt + y*yt + z*zt)  = d/2, two targets per packed op
#pragma unroll
        for (int j = 0; j < 4; j++)
            asm("fma.rn.f32x2 %0, %1, %2, %3;" : "=l"(m[j]) : "l"(qb.x), "l"(NZ[j]), "l"(HT[j]));
#pragma unroll
        for (int j = 0; j < 4; j++)
            asm("fma.rn.f32x2 %0, %1, %2, %0;" : "+l"(m[j]) : "l"(qa.y), "l"(NY[j]));
#pragma unroll
        for (int j = 0; j < 4; j++)
            asm("fma.rn.f32x2 %0, %1, %2, %0;" : "+l"(m[j]) : "l"(qa.x), "l"(NX[j]));
#pragma unroll
        for (int j = 0; j < 4; j++)
            asm("add.rn.f32x2 %0, %0, %1;" : "+l"(m[j]) : "l"(qb.y));   // + hq

        float rmin;
        {
            float2 e0 = reinterpret_cast<float2&>(m[0]);
            float2 e1 = reinterpret_cast<float2&>(m[1]);
            float2 e2 = reinterpret_cast<float2&>(m[2]);
            float2 e3 = reinterpret_cast<float2&>(m[3]);
            // column mins (per lane-owned target)
            cl[0] = fminf(cl[0], e0.x); cl[1] = fminf(cl[1], e0.y);
            cl[2] = fminf(cl[2], e1.x); cl[3] = fminf(cl[3], e1.y);
            cl[4] = fminf(cl[4], e2.x); cl[5] = fminf(cl[5], e2.y);
            cl[6] = fminf(cl[6], e3.x); cl[7] = fminf(cl[7], e3.y);
            // row min over this lane's 8 targets
            float r0 = fminf(e0.x, e0.y), r1 = fminf(e1.x, e1.y);
            float r2 = fminf(e2.x, e2.y), r3 = fminf(e3.x, e3.y);
            rmin = fminf(fminf(r0, r1), fminf(r2, r3));
        }
        // warp-wide row min via single REDUX on the order-preserving encoding
        unsigned u = __reduce_min_sync(0xFFFFFFFFu, fenc(rmin));
        if (ln == 0) atomicMax(&enc1[q], ~u);
    }

    // ---- Publish column mins (8 per lane, all 4 warps feed the same 256 targets) ----
#pragma unroll
    for (int i = 0; i < 8; i++)
        atomicMax(&enc2[ln * 8 + i], ~fenc(cl[i]));

    // ---- Grid-wide ticket reduction (last NSLICE CTAs sweep; dist = 2*m_min) ----
    __threadfence();
    if (t == 0) s_tk = atomicAdd(&g_tk1, 1u);
    __syncthreads();
    unsigned tk = s_tk;
    if (tk < NCTA - NSLICE) return;

    if (t == 0) { while (*(volatile unsigned*)&g_tk1 < (unsigned)NCTA) {} }
    __syncthreads();
    __threadfence();

    int slice = (int)tk - (NCTA - NSLICE);         // 0..63
    int base  = slice * (2 * ASZ / NSLICE);        // 1024 entries per slice
    float s = 0.f;
#pragma unroll
    for (int i = 0; i < 8; i++) {
        int idx = base + t + i * TPB;
        unsigned u = g_enc[idx];
        g_enc[idx] = 0u;                           // reset for next graph replay
        s += fdec(~u);
    }
#pragma unroll
    for (int o = 16; o > 0; o >>= 1) s += __shfl_down_sync(0xFFFFFFFFu, s, o);
    if ((t & 31) == 0) wsum[t >> 5] = s;
    __syncthreads();
    if (t == 0) {
        g_part[slice] = (wsum[0] + wsum[1]) + (wsum[2] + wsum[3]);
        __threadfence();
        s_tk = atomicAdd(&g_tk2, 1u);
    }
    __syncthreads();

    if (s_tk == NSLICE - 1 && t < 32) {            // last slice CTA folds partials
        __threadfence();
        float v = g_part[t] + g_part[t + 32];
#pragma unroll
        for (int o = 16; o > 0; o >>= 1) v += __shfl_down_sync(0xFFFFFFFFu, v, o);
        if (t == 0) {
            out[0] = v * (2.0f / (float)(NB * NPTS));   // dist = 2*m
            g_tk1 = 0u;
            g_tk2 = 0u;
        }
    }
}

extern "C" void kernel_launch(void* const* d_in, const int* in_sizes, int n_in,
                              void* d_out, int out_size) {
    const float* a1 = (const float*)d_in[0];   // array1 [4,8192,3]
    const float* a2 = (const float*)d_in[1];   // array2 [4,8192,3]
    float* out = (float*)d_out;

    dim3 grid(NPTS / QBLK, NPTS / TBLK, NB);   // (16, 32, 4) = 2048 CTAs
    chamfer_kernel<<<grid, TPB>>>(a1, a2, out);
}

// round 15
// speedup vs baseline: 1.1008x; 1.1008x over previous
#include <cuda_runtime.h>

#define NB     4
#define NPTS   8192
#define TPB    128
#define QBLK   128            // queries per block (ring groups of 32)
#define TBLK   1024           // targets per block (256/warp, 8/lane)
#define ASZ    (NB*NPTS)      // 32768 points per array
#define NCTA   2048
#define NSLICE 64

// Scratch (zero-initialized device globals; no allocations):
// g_enc[idx] = ~fenc(min_m), m = half squared distance. 0 == +inf identity for
// atomicMax; the reduction resets entries to 0 => identical state every replay.
__device__ unsigned g_enc[2*ASZ];   // [0,ASZ): a1 row mins ; [ASZ,2ASZ): a2 col mins
__device__ float    g_part[NSLICE];
__device__ unsigned g_tk1, g_tk2;

__device__ __forceinline__ unsigned long long pk2(float lo, float hi) {
    unsigned long long r;
    asm("mov.b64 %0, {%1,%2};" : "=l"(r) : "f"(lo), "f"(hi));
    return r;
}
__device__ __forceinline__ unsigned fenc(float f) {
    unsigned b = __float_as_uint(f);
    return b ^ ((b & 0x80000000u) ? 0xFFFFFFFFu : 0x80000000u);
}
__device__ __forceinline__ float fdec(unsigned u) {
    unsigned b = (u & 0x80000000u) ? (u ^ 0x80000000u) : ~u;
    return __uint_as_float(b);
}

// Symmetric single-pass: every (a1,a2) pair evaluated ONCE, feeding both mins.
// grid (64, 8, 4): x = a1 query tile (128), y = a2 target tile (1024), z = batch.
// Lane owns 8 targets (4 packed pairs) in registers; queries stream from smem.
// Row mins ride a shfl ring (1 shfl/step); col mins live in registers.
__global__ __launch_bounds__(TPB) void chamfer_kernel(const float* __restrict__ q1,
                                                      const float* __restrict__ q2,
                                                      float* __restrict__ out) {
    int b  = blockIdx.z;
    int t  = threadIdx.x;
    int ln = t & 31;
    int w  = t >> 5;

    __shared__ ulonglong2 qsh[QBLK * 2];   // 4 KB: per query {X2,Y2},{Z2,HQ2}
    __shared__ float      tsm[TBLK * 3];   // 12 KB raw target staging
    __shared__ unsigned   s_tk;
    __shared__ float      wsum[4];

    // ---- Stage queries: thread t packs query t (dup splats + hq) ----
    {
        const float* qp = q1 + (size_t)(b * NPTS + blockIdx.x * QBLK + t) * 3;
        float x = qp[0], y = qp[1], z = qp[2];
        float h = 0.5f * (x*x + y*y + z*z);
        qsh[2*t    ] = make_ulonglong2(pk2(x, x), pk2(y, y));
        qsh[2*t + 1] = make_ulonglong2(pk2(z, z), pk2(h, h));
    }
    // ---- Stage targets raw: 1024 points = 768 float4 ----
    {
        const float4* ts = (const float4*)(q2 + (size_t)(b * NPTS + blockIdx.y * TBLK) * 3);
        float4* dst = (float4*)tsm;
        for (int i = t; i < (TBLK * 3) / 4; i += TPB) dst[i] = ts[i];
    }
    __syncthreads();

    // ---- Lane-resident packed targets: {(-x0,-x1),(-y0,-y1),(-z0,-z1),(ht0,ht1)} ----
    unsigned long long NX[4], NY[4], NZ[4], HT[4];
    float cl[8];
#pragma unroll
    for (int j = 0; j < 4; j++) {
        const float* p = &tsm[(w * 256 + ln * 8 + 2 * j) * 3];
        float x0 = p[0], y0 = p[1], z0 = p[2];
        float x1 = p[3], y1 = p[4], z1 = p[5];
        NX[j] = pk2(-x0, -x1);
        NY[j] = pk2(-y0, -y1);
        NZ[j] = pk2(-z0, -z1);
        HT[j] = pk2(0.5f*(x0*x0 + y0*y0 + z0*z0), 0.5f*(x1*x1 + y1*y1 + z1*z1));
        cl[2*j]     = __int_as_float(0x7f800000);
        cl[2*j + 1] = __int_as_float(0x7f800000);
    }
    const unsigned long long ONE2 = pk2(1.0f, 1.0f);

    unsigned* enc1 = g_enc + b * NPTS + blockIdx.x * QBLK;
    unsigned* enc2 = g_enc + ASZ + b * NPTS + blockIdx.y * TBLK + w * 256 + ln * 8;
    int nxt = (ln + 1) & 31;

    // ---- Main loop: 4 ring groups of 32 queries ----
    for (int g = 0; g < 4; ++g) {
        const ulonglong2* qg = &qsh[g * 64];
        float acc = __int_as_float(0x7f800000);
#pragma unroll 8
        for (int s = 0; s < 32; ++s) {
            int q = (ln + s) & 31;
            ulonglong2 u0 = qg[2*q];        // X2, Y2
            ulonglong2 u1 = qg[2*q + 1];    // Z2, HQ2
            // Ring: pass current acc (query (ln+s-1)) to lane ln-1; receive the
            // acc for query (ln+s). Issued early; consumed at step end (lat hidden).
            float xin = __shfl_sync(0xFFFFFFFFu, acc, nxt);

            unsigned long long m[4];
            // m = hq + ht - q.t  (= half squared distance), 2 targets per op.
#pragma unroll
            for (int j = 0; j < 4; j++)
                asm("fma.rn.f32x2 %0, %1, %2, %3;" : "=l"(m[j]) : "l"(u1.y), "l"(ONE2),  "l"(HT[j]));
#pragma unroll
            for (int j = 0; j < 4; j++)
                asm("fma.rn.f32x2 %0, %1, %2, %0;" : "+l"(m[j]) : "l"(u1.x), "l"(NZ[j]));
#pragma unroll
            for (int j = 0; j < 4; j++)
                asm("fma.rn.f32x2 %0, %1, %2, %0;" : "+l"(m[j]) : "l"(u0.y), "l"(NY[j]));
#pragma unroll
            for (int j = 0; j < 4; j++)
                asm("fma.rn.f32x2 %0, %1, %2, %0;" : "+l"(m[j]) : "l"(u0.x), "l"(NX[j]));

            float2 e0 = reinterpret_cast<float2&>(m[0]);
            float2 e1 = reinterpret_cast<float2&>(m[1]);
            float2 e2 = reinterpret_cast<float2&>(m[2]);
            float2 e3 = reinterpret_cast<float2&>(m[3]);
            // col mins (register-resident, per lane-owned target)
            cl[0] = fminf(cl[0], e0.x); cl[1] = fminf(cl[1], e0.y);
            cl[2] = fminf(cl[2], e1.x); cl[3] = fminf(cl[3], e1.y);
            cl[4] = fminf(cl[4], e2.x); cl[5] = fminf(cl[5], e2.y);
            cl[6] = fminf(cl[6], e3.x); cl[7] = fminf(cl[7], e3.y);
            // row min over this lane's 8 targets, fold into the ring acc
            float r0 = fminf(e0.x, e0.y), r1 = fminf(e1.x, e1.y);
            float r2 = fminf(e2.x, e2.y), r3 = fminf(e3.x, e3.y);
            acc = fminf(xin, fminf(fminf(r0, r1), fminf(r2, r3)));
        }
        // acc now holds the complete 256-target min for query (ln+31)&31
        int qf = (ln + 31) & 31;
        atomicMax(&enc1[g * 32 + qf], ~fenc(acc));
    }

    // ---- Publish col mins (min over this block's 128 queries) ----
#pragma unroll
    for (int i = 0; i < 8; i++)
        atomicMax(&enc2[i], ~fenc(cl[i]));

    // ---- Grid-wide ticket reduction (last NSLICE CTAs sweep; dist = 2*m) ----
    __threadfence();
    if (t == 0) s_tk = atomicAdd(&g_tk1, 1u);
    __syncthreads();
    unsigned tk = s_tk;
    if (tk < NCTA - NSLICE) return;

    if (t == 0) { while (*(volatile unsigned*)&g_tk1 < (unsigned)NCTA) {} }
    __syncthreads();
    __threadfence();

    int slice = (int)tk - (NCTA - NSLICE);     // 0..63
    int base  = slice * (2 * ASZ / NSLICE);    // 1024 entries per slice
    float s = 0.f;
#pragma unroll
    for (int i = 0; i < 8; i++) {
        int idx = base + t + i * TPB;
        unsigned u = g_enc[idx];
        g_enc[idx] = 0u;                       // reset for next graph replay
        s += fdec(~u);
    }
#pragma unroll
    for (int o = 16; o > 0; o >>= 1) s += __shfl_down_sync(0xFFFFFFFFu, s, o);
    if ((t & 31) == 0) wsum[t >> 5] = s;
    __syncthreads();
    if (t == 0) {
        g_part[slice] = (wsum[0] + wsum[1]) + (wsum[2] + wsum[3]);
        __threadfence();
        s_tk = atomicAdd(&g_tk2, 1u);
    }
    __syncthreads();

    if (s_tk == NSLICE - 1 && t < 32) {        // last slice CTA folds partials
        __threadfence();
        float v = g_part[t] + g_part[t + 32];
#pragma unroll
        for (int o = 16; o > 0; o >>= 1) v += __shfl_down_sync(0xFFFFFFFFu, v, o);
        if (t == 0) {
            out[0] = v * (2.0f / (float)(NB * NPTS));   // dist = 2*m
            g_tk1 = 0u;
            g_tk2 = 0u;
        }
    }
}

extern "C" void kernel_launch(void* const* d_in, const int* in_sizes, int n_in,
                              void* d_out, int out_size) {
    const float* a1 = (const float*)d_in[0];   // array1 [4,8192,3]
    const float* a2 = (const float*)d_in[1];   // array2 [4,8192,3]
    float* out = (float*)d_out;

    dim3 grid(NPTS / QBLK, NPTS / TBLK, NB);   // (64, 8, 4) = 2048 CTAs
    chamfer_kernel<<<grid, TPB>>>(a1, a2, out);
}

// round 16
// speedup vs baseline: 1.1993x; 1.0895x over previous
#include <cuda_runtime.h>

#define NB     4
#define NPTS   8192
#define TPB    128
#define QBLK   256            // queries per block (8 per lane, same for all warps)
#define TBLK   1024           // targets per block (256 per warp, 8 per lane-group)
#define ASZ    (NB*NPTS)
#define NCTA   1024
#define NSLICE 64

// Zero-initialized device scratch (no allocations). g_enc[idx] = ~fenc(min_m),
// m = half squared distance. 0 == +inf identity for atomicMax; the reduction
// resets entries to 0 so every graph replay starts identically.
__device__ unsigned g_enc[2*ASZ];   // [0,ASZ): a1 row mins ; [ASZ,2ASZ): a2 col mins
__device__ float    g_part[NSLICE];
__device__ unsigned g_tk1, g_tk2;

__device__ __forceinline__ unsigned long long pk2(float lo, float hi) {
    unsigned long long r;
    asm("mov.b64 %0, {%1,%2};" : "=l"(r) : "f"(lo), "f"(hi));
    return r;
}
__device__ __forceinline__ unsigned fenc(float f) {
    unsigned b = __float_as_uint(f);
    return b ^ ((b & 0x80000000u) ? 0xFFFFFFFFu : 0x80000000u);
}
__device__ __forceinline__ float fdec(unsigned u) {
    unsigned b = (u & 0x80000000u) ? (u ^ 0x80000000u) : ~u;
    return __uint_as_float(b);
}

// Symmetric systolic: every (a1,a2) pair evaluated ONCE; row accs lane-private,
// col accs rotate through the warp (8 shfl per ~400-cyc step, off critical path).
// grid (32, 8, 4): x = a1 tile (256), y = a2 tile (1024), z = batch.
__global__ __launch_bounds__(TPB) void chamfer_kernel(const float* __restrict__ a1,
                                                      const float* __restrict__ a2,
                                                      float* __restrict__ out) {
    int b  = blockIdx.z;
    int t  = threadIdx.x;
    int ln = t & 31;
    int w  = t >> 5;

    // Target splats: per warp 32 groups x 17 ulonglong2 (272B stride: 17*16B;
    // 17p mod 8 distinct within each 8-lane phase -> conflict-free LDS.128).
    // Group g, target i: [2i] = {(-x,-x),(-y,-y)}, [2i+1] = {(-z,-z),(ht,ht)}.
    __shared__ ulonglong2 tspl[4][32][17];   // ~34.8 KB
    __shared__ unsigned   s_tk;
    __shared__ float      wsum[4];

    // ---- Stage this lane's 8 targets as splats (8 points = 6 float4, aligned) ----
    {
        const float* tp = a2 + (size_t)(b * NPTS + blockIdx.y * TBLK + w * 256 + ln * 8) * 3;
#pragma unroll
        for (int i = 0; i < 8; i++) {
            float x = tp[3*i], y = tp[3*i+1], z = tp[3*i+2];
            float ht = 0.5f * (x*x + y*y + z*z);
            tspl[w][ln][2*i    ] = make_ulonglong2(pk2(-x, -x), pk2(-y, -y));
            tspl[w][ln][2*i + 1] = make_ulonglong2(pk2(-z, -z), pk2(ht, ht));
        }
    }

    // ---- Lane-private queries: 8 points packed as 4 pairs ----
    unsigned long long QX[4], QY[4], QZ[4], QH[4];
    {
        const float* qp = a1 + (size_t)(b * NPTS + blockIdx.x * QBLK + ln * 8) * 3;
#pragma unroll
        for (int j = 0; j < 4; j++) {
            float x0 = qp[6*j],   y0 = qp[6*j+1], z0 = qp[6*j+2];
            float x1 = qp[6*j+3], y1 = qp[6*j+4], z1 = qp[6*j+5];
            QX[j] = pk2(x0, x1);
            QY[j] = pk2(y0, y1);
            QZ[j] = pk2(z0, z1);
            QH[j] = pk2(0.5f*(x0*x0 + y0*y0 + z0*z0), 0.5f*(x1*x1 + y1*y1 + z1*z1));
        }
    }

    float rowacc[8], colacc[8];
#pragma unroll
    for (int i = 0; i < 8; i++) {
        rowacc[i] = __int_as_float(0x7f800000);
        colacc[i] = __int_as_float(0x7f800000);
    }
    __syncthreads();

    // ---- Systolic main loop: 32 steps; step s pairs lane ln with tgroup (ln+s)&31 ----
    for (int s = 0; s < 32; ++s) {
        int p = (ln + s) & 31;
        const ulonglong2* tg = tspl[w][p];
#pragma unroll
        for (int i = 0; i < 8; ++i) {        // 8 targets of the partner group
            ulonglong2 ta = tg[2*i];         // (-x,-x), (-y,-y)
            ulonglong2 tb = tg[2*i + 1];     // (-z,-z), (ht,ht)
            float cmin = __int_as_float(0x7f800000);
#pragma unroll
            for (int j = 0; j < 4; ++j) {    // 4 query pairs = 8 queries
                unsigned long long m;
                // m = hq + ht - q.t  (half squared distance), 2 queries per op
                asm("fma.rn.f32x2 %0, %1, %2, %3;" : "=l"(m) : "l"(QZ[j]), "l"(tb.x), "l"(tb.y));
                asm("fma.rn.f32x2 %0, %1, %2, %0;" : "+l"(m) : "l"(QY[j]), "l"(ta.y));
                asm("fma.rn.f32x2 %0, %1, %2, %0;" : "+l"(m) : "l"(QX[j]), "l"(ta.x));
                asm("add.rn.f32x2 %0, %0, %1;"     : "+l"(m) : "l"(QH[j]));
                float2 e = reinterpret_cast<float2&>(m);
                rowacc[2*j]     = fminf(rowacc[2*j],     e.x);
                rowacc[2*j + 1] = fminf(rowacc[2*j + 1], e.y);
                cmin = fminf(cmin, fminf(e.x, e.y));
            }
            colacc[i] = fminf(colacc[i], cmin);
        }
        // Rotate col accs one lane over (receive from lane ln+1). After 32
        // rotations the accumulators are back home. Latency hidden by the step.
#pragma unroll
        for (int i = 0; i < 8; i++)
            colacc[i] = __shfl_sync(0xFFFFFFFFu, colacc[i], (ln + 1) & 31);
    }

    // ---- Epilogue: all accumulators are lane-private; one atomic each ----
    {
        unsigned* enc1 = g_enc + b * NPTS + blockIdx.x * QBLK + ln * 8;
        unsigned* enc2 = g_enc + ASZ + b * NPTS + blockIdx.y * TBLK + w * 256 + ln * 8;
#pragma unroll
        for (int i = 0; i < 8; i++) atomicMax(&enc1[i], ~fenc(rowacc[i]));
#pragma unroll
        for (int i = 0; i < 8; i++) atomicMax(&enc2[i], ~fenc(colacc[i]));
    }

    // ---- Grid-wide ticket reduction (last NSLICE CTAs sweep; dist = 2*m) ----
    __threadfence();
    if (t == 0) s_tk = atomicAdd(&g_tk1, 1u);
    __syncthreads();
    unsigned tk = s_tk;
    if (tk < NCTA - NSLICE) return;

    if (t == 0) { while (*(volatile unsigned*)&g_tk1 < (unsigned)NCTA) {} }
    __syncthreads();
    __threadfence();

    int slice = (int)tk - (NCTA - NSLICE);     // 0..63
    int base  = slice * (2 * ASZ / NSLICE);    // 1024 entries per slice
    float s = 0.f;
#pragma unroll
    for (int i = 0; i < 8; i++) {
        int idx = base + t + i * TPB;
        unsigned u = g_enc[idx];
        g_enc[idx] = 0u;                       // reset for next graph replay
        s += fdec(~u);
    }
#pragma unroll
    for (int o = 16; o > 0; o >>= 1) s += __shfl_down_sync(0xFFFFFFFFu, s, o);
    if ((t & 31) == 0) wsum[t >> 5] = s;
    __syncthreads();
    if (t == 0) {
        g_part[slice] = (wsum[0] + wsum[1]) + (wsum[2] + wsum[3]);
        __threadfence();
        s_tk = atomicAdd(&g_tk2, 1u);
    }
    __syncthreads();

    if (s_tk == NSLICE - 1 && t < 32) {        // last slice CTA folds partials
        __threadfence();
        float v = g_part[t] + g_part[t + 32];
#pragma unroll
        for (int o = 16; o > 0; o >>= 1) v += __shfl_down_sync(0xFFFFFFFFu, v, o);
        if (t == 0) {
            out[0] = v * (2.0f / (float)(NB * NPTS));   // dist = 2*m
            g_tk1 = 0u;
            g_tk2 = 0u;
        }
    }
}

extern "C" void kernel_launch(void* const* d_in, const int* in_sizes, int n_in,
                              void* d_out, int out_size) {
    const float* a1 = (const float*)d_in[0];   // array1 [4,8192,3]
    const float* a2 = (const float*)d_in[1];   // array2 [4,8192,3]
    float* out = (float*)d_out;

    dim3 grid(NPTS / QBLK, NPTS / TBLK, NB);   // (32, 8, 4) = 1024 CTAs, one wave
    chamfer_kernel<<<grid, TPB>>>(a1, a2, out);
}

// round 17
// speedup vs baseline: 1.2591x; 1.0499x over previous
#include <cuda_runtime.h>

#define NB     4
#define NPTS   8192
#define TPB    128
#define QBLK   256            // queries per block (8 per lane, shared by warps)
#define TBLK   512            // targets per block (128 per warp: 32 groups x 4)
#define ASZ    (NB*NPTS)
#define NCTA   2048
#define NSLICE 64

// Zero-initialized device scratch (no allocations). g_enc[idx] = ~fenc(min_m),
// m = half squared distance. 0 == +inf identity for atomicMax; the reduction
// resets entries to 0 so every graph replay starts identically.
__device__ unsigned g_enc[2*ASZ];   // [0,ASZ): a1 row mins ; [ASZ,2ASZ): a2 col mins
__device__ float    g_part[NSLICE];
__device__ unsigned g_tk1, g_tk2;

__device__ __forceinline__ unsigned long long pk2(float lo, float hi) {
    unsigned long long r;
    asm("mov.b64 %0, {%1,%2};" : "=l"(r) : "f"(lo), "f"(hi));
    return r;
}
__device__ __forceinline__ unsigned fenc(float f) {
    unsigned b = __float_as_uint(f);
    return b ^ ((b & 0x80000000u) ? 0xFFFFFFFFu : 0x80000000u);
}
__device__ __forceinline__ float fdec(unsigned u) {
    unsigned b = (u & 0x80000000u) ? (u ^ 0x80000000u) : ~u;
    return __uint_as_float(b);
}

// Symmetric systolic: every (a1,a2) pair evaluated ONCE. Lane owns 8 queries
// (packed pairs, registers) + the col accs of one 4-target group; col accs
// rotate one lane per step (4 shfl / ~200-cyc step, off the critical chain).
// grid (32, 16, 4) = 2048 CTAs (~2.3 waves -> straggler smoothing).
__global__ __launch_bounds__(TPB) void chamfer_kernel(const float* __restrict__ a1,
                                                      const float* __restrict__ a2,
                                                      float* __restrict__ out) {
    int b  = blockIdx.z;
    int t  = threadIdx.x;
    int ln = t & 31;
    int w  = t >> 5;

    // Target splats: per warp 32 groups x 9 ulonglong2 (144B stride; 144B/4 = 36
    // banks = 4 mod 32 -> 8-lane LDS.128 phases hit distinct banks).
    // Group g, target i: [2i] = {(-x,-x),(-y,-y)}, [2i+1] = {(-z,-z),(ht,ht)}.
    __shared__ ulonglong2 tspl[4][32][9];   // 18.4 KB
    __shared__ unsigned   s_tk;
    __shared__ float      wsum[4];

    // ---- Stage this lane's target group (4 points = 3 float4, aligned) ----
    {
        const float* tp = a2 + (size_t)(b * NPTS + blockIdx.y * TBLK + w * 128 + ln * 4) * 3;
        float4 A = ((const float4*)tp)[0];
        float4 B = ((const float4*)tp)[1];
        float4 C = ((const float4*)tp)[2];
        // targets: (A.x,A.y,A.z) (A.w,B.x,B.y) (B.z,B.w,C.x) (C.y,C.z,C.w)
        float h0 = 0.5f*(A.x*A.x + A.y*A.y + A.z*A.z);
        float h1 = 0.5f*(A.w*A.w + B.x*B.x + B.y*B.y);
        float h2 = 0.5f*(B.z*B.z + B.w*B.w + C.x*C.x);
        float h3 = 0.5f*(C.y*C.y + C.z*C.z + C.w*C.w);
        ulonglong2* g = tspl[w][ln];
        g[0] = make_ulonglong2(pk2(-A.x, -A.x), pk2(-A.y, -A.y));
        g[1] = make_ulonglong2(pk2(-A.z, -A.z), pk2( h0,   h0));
        g[2] = make_ulonglong2(pk2(-A.w, -A.w), pk2(-B.x, -B.x));
        g[3] = make_ulonglong2(pk2(-B.y, -B.y), pk2( h1,   h1));
        g[4] = make_ulonglong2(pk2(-B.z, -B.z), pk2(-B.w, -B.w));
        g[5] = make_ulonglong2(pk2(-C.x, -C.x), pk2( h2,   h2));
        g[6] = make_ulonglong2(pk2(-C.y, -C.y), pk2(-C.z, -C.z));
        g[7] = make_ulonglong2(pk2(-C.w, -C.w), pk2( h3,   h3));
    }

    // ---- Lane-private queries: 8 points packed as 4 pairs ----
    unsigned long long QX[4], QY[4], QZ[4], QH[4];
    {
        const float* qp = a1 + (size_t)(b * NPTS + blockIdx.x * QBLK + ln * 8) * 3;
#pragma unroll
        for (int j = 0; j < 4; j++) {
            float x0 = qp[6*j],   y0 = qp[6*j+1], z0 = qp[6*j+2];
            float x1 = qp[6*j+3], y1 = qp[6*j+4], z1 = qp[6*j+5];
            QX[j] = pk2(x0, x1);
            QY[j] = pk2(y0, y1);
            QZ[j] = pk2(z0, z1);
            QH[j] = pk2(0.5f*(x0*x0 + y0*y0 + z0*z0), 0.5f*(x1*x1 + y1*y1 + z1*z1));
        }
    }

    float rowacc[8], colacc[4];
#pragma unroll
    for (int i = 0; i < 8; i++) rowacc[i] = __int_as_float(0x7f800000);
#pragma unroll
    for (int i = 0; i < 4; i++) colacc[i] = __int_as_float(0x7f800000);
    __syncthreads();

    // ---- Systolic loop: 32 steps; step s pairs lane ln with group (ln+s)&31 ----
#pragma unroll 2
    for (int s = 0; s < 32; ++s) {
        int p = (ln + s) & 31;
        const ulonglong2* tg = tspl[w][p];
#pragma unroll
        for (int i = 0; i < 4; ++i) {        // 4 targets of the partner group
            ulonglong2 ta = tg[2*i];         // (-x,-x), (-y,-y)
            ulonglong2 tb = tg[2*i + 1];     // (-z,-z), (ht,ht)
            unsigned long long m[4];
            // m = hq + ht - q.t  (half squared distance), 2 queries per op
#pragma unroll
            for (int j = 0; j < 4; ++j)
                asm("fma.rn.f32x2 %0, %1, %2, %3;" : "=l"(m[j]) : "l"(QZ[j]), "l"(tb.x), "l"(tb.y));
#pragma unroll
            for (int j = 0; j < 4; ++j)
                asm("fma.rn.f32x2 %0, %1, %2, %0;" : "+l"(m[j]) : "l"(QY[j]), "l"(ta.y));
#pragma unroll
            for (int j = 0; j < 4; ++j)
                asm("fma.rn.f32x2 %0, %1, %2, %0;" : "+l"(m[j]) : "l"(QX[j]), "l"(ta.x));
#pragma unroll
            for (int j = 0; j < 4; ++j)
                asm("add.rn.f32x2 %0, %0, %1;"     : "+l"(m[j]) : "l"(QH[j]));

            float2 e0 = reinterpret_cast<float2&>(m[0]);
            float2 e1 = reinterpret_cast<float2&>(m[1]);
            float2 e2 = reinterpret_cast<float2&>(m[2]);
            float2 e3 = reinterpret_cast<float2&>(m[3]);
            rowacc[0] = fminf(rowacc[0], e0.x); rowacc[1] = fminf(rowacc[1], e0.y);
            rowacc[2] = fminf(rowacc[2], e1.x); rowacc[3] = fminf(rowacc[3], e1.y);
            rowacc[4] = fminf(rowacc[4], e2.x); rowacc[5] = fminf(rowacc[5], e2.y);
            rowacc[6] = fminf(rowacc[6], e3.x); rowacc[7] = fminf(rowacc[7], e3.y);
            // col min over the 8 queries: 7-op tree + 1 accumulate
            float u0 = fminf(e0.x, e0.y), u1 = fminf(e1.x, e1.y);
            float u2 = fminf(e2.x, e2.y), u3 = fminf(e3.x, e3.y);
            colacc[i] = fminf(colacc[i], fminf(fminf(u0, u1), fminf(u2, u3)));
        }
        // Rotate col accs one lane (receive from ln+1); home after 32 steps.
#pragma unroll
        for (int i = 0; i < 4; i++)
            colacc[i] = __shfl_sync(0xFFFFFFFFu, colacc[i], (ln + 1) & 31);
    }

    // ---- Epilogue: everything lane-private; one atomic per slot ----
    {
        unsigned* enc1 = g_enc + b * NPTS + blockIdx.x * QBLK + ln * 8;
        unsigned* enc2 = g_enc + ASZ + b * NPTS + blockIdx.y * TBLK + w * 128 + ln * 4;
#pragma unroll
        for (int i = 0; i < 8; i++) atomicMax(&enc1[i], ~fenc(rowacc[i]));
#pragma unroll
        for (int i = 0; i < 4; i++) atomicMax(&enc2[i], ~fenc(colacc[i]));
    }

    // ---- Grid-wide ticket reduction (last NSLICE CTAs sweep; dist = 2*m) ----
    __threadfence();
    if (t == 0) s_tk = atomicAdd(&g_tk1, 1u);
    __syncthreads();
    unsigned tk = s_tk;
    if (tk < NCTA - NSLICE) return;

    if (t == 0) { while (*(volatile unsigned*)&g_tk1 < (unsigned)NCTA) {} }
    __syncthreads();
    __threadfence();

    int slice = (int)tk - (NCTA - NSLICE);     // 0..63
    int base  = slice * (2 * ASZ / NSLICE);    // 1024 entries per slice
    float s = 0.f;
#pragma unroll
    for (int i = 0; i < 8; i++) {
        int idx = base + t + i * TPB;
        unsigned u = g_enc[idx];
        g_enc[idx] = 0u;                       // reset for next graph replay
        s += fdec(~u);
    }
#pragma unroll
    for (int o = 16; o > 0; o >>= 1) s += __shfl_down_sync(0xFFFFFFFFu, s, o);
    if ((t & 31) == 0) wsum[t >> 5] = s;
    __syncthreads();
    if (t == 0) {
        g_part[slice] = (wsum[0] + wsum[1]) + (wsum[2] + wsum[3]);
        __threadfence();
        s_tk = atomicAdd(&g_tk2, 1u);
    }
    __syncthreads();

    if (s_tk == NSLICE - 1 && t < 32) {        // last slice CTA folds partials
        __threadfence();
        float v = g_part[t] + g_part[t + 32];
#pragma unroll
        for (int o = 16; o > 0; o >>= 1) v += __shfl_down_sync(0xFFFFFFFFu, v, o);
        if (t == 0) {
            out[0] = v * (2.0f / (float)(NB * NPTS));   // dist = 2*m
            g_tk1 = 0u;
            g_tk2 = 0u;
        }
    }
}

extern "C" void kernel_launch(void* const* d_in, const int* in_sizes, int n_in,
                              void* d_out, int out_size) {
    const float* a1 = (const float*)d_in[0];   // array1 [4,8192,3]
    const float* a2 = (const float*)d_in[1];   // array2 [4,8192,3]
    float* out = (float*)d_out;

    dim3 grid(NPTS / QBLK, NPTS / TBLK, NB);   // (32, 16, 4) = 2048 CTAs
    chamfer_kernel<<<grid, TPB>>>(a1, a2, out);
}